// round 2
// baseline (speedup 1.0000x reference)
#include <cuda_runtime.h>
#include <math.h>

#define IN_CH  256
#define OUT_CH 256
#define BATCH  16
#define HDIM   128
#define WDIM   128

// Transposed, pre-scaled weights: wT[t][ic][oc], t = kh*3+kw. 2.36 MB scratch.
__device__ float g_wT[9 * IN_CH * OUT_CH];

// ---------------------------------------------------------------------------
// Kernel 1: weight transform  w[oc][ic][kh][kw]*scale -> wT[t][ic][oc]
// Tiny one-shot (2.3 MB); uncoalesced reads are fine (~few us).
// ---------------------------------------------------------------------------
__global__ void weight_transform_kernel(const float* __restrict__ w, float scale) {
    int gid = blockIdx.x * blockDim.x + threadIdx.x;
    if (gid >= 9 * IN_CH * OUT_CH) return;
    int oc   = gid & 255;
    int rest = gid >> 8;
    int ic   = rest & 255;
    int t    = rest >> 8;            // 0..8
    g_wT[gid] = w[oc * (IN_CH * 9) + ic * 9 + t] * scale;
}

// ---------------------------------------------------------------------------
// Kernel 2: implicit-GEMM conv.
//   M = B*H*W (one block M-tile = one image row, 128 w-positions)
//   N = OUT_CH, K = 9*IN_CH = 2304 (outer: 9 taps, inner: 32 ic-chunks of 8)
// Block tile 128x128, BK=8, thread tile 8x8, 256 threads, double-buffered.
// ---------------------------------------------------------------------------
__global__ __launch_bounds__(256, 2)
void conv_gemm_kernel(const float* __restrict__ x,
                      const float* __restrict__ cond,
                      const float* __restrict__ bias,
                      float* __restrict__ out) {
    __shared__ float As[2][8][128];   // [buf][k][m(w)]
    __shared__ float Bs[2][8][128];   // [buf][k][n(oc)]
    __shared__ float cond_s[IN_CH];

    const int tid = threadIdx.x;
    const int n0  = blockIdx.x << 7;       // 0 or 128
    const int mt  = blockIdx.y;            // 0..2047
    const int b   = mt >> 7;
    const int h   = mt & 127;

    // Stage this batch's cond row
    cond_s[tid & 255] = cond[b * IN_CH + (tid & 255)];
    __syncthreads();

    // Loader lane mapping: 256 threads -> 8 k-rows x 32 quads of 4 floats
    const int lk  = tid >> 5;              // 0..7
    const int lw4 = (tid & 31) << 2;       // 0,4,...,124

    const float* xb = x + (size_t)b * IN_CH * HDIM * WDIM;

    float  aReg[4];
    float4 bReg;

    const int tx = tid & 15;
    const int ty = tid >> 4;
    float acc[8][8];
    #pragma unroll
    for (int i = 0; i < 8; i++)
        #pragma unroll
        for (int j = 0; j < 8; j++) acc[i][j] = 0.f;

    // ---- tile loader (global -> regs) ----
    // kstep in [0,288): tap t = kstep>>5, ic0 = (kstep&31)<<3
    #define LOAD_TILE(kstep) do {                                              \
        int t_   = (kstep) >> 5;                                               \
        int ic0_ = ((kstep) & 31) << 3;                                        \
        int kh_  = t_ / 3;                                                     \
        int kw_  = t_ - kh_ * 3;                                               \
        int hh_  = h + kh_ - 1;                                                \
        int ic_  = ic0_ + lk;                                                  \
        float c_ = cond_s[ic_];                                                \
        if ((unsigned)hh_ < (unsigned)HDIM) {                                  \
            const float* row_ = xb + ((size_t)ic_ * HDIM + hh_) * WDIM;        \
            _Pragma("unroll")                                                  \
            for (int j_ = 0; j_ < 4; j_++) {                                   \
                int ws_ = lw4 + j_ + kw_ - 1;                                  \
                aReg[j_] = ((unsigned)ws_ < (unsigned)WDIM)                    \
                             ? row_[ws_] * c_ : 0.f;                           \
            }                                                                  \
        } else {                                                               \
            aReg[0] = aReg[1] = aReg[2] = aReg[3] = 0.f;                       \
        }                                                                      \
        bReg = *reinterpret_cast<const float4*>(                               \
            &g_wT[(t_ << 16) + (ic_ << 8) + n0 + lw4]);                        \
    } while (0)

    #define STORE_TILE(buf) do {                                               \
        *reinterpret_cast<float4*>(&As[(buf)][lk][lw4]) =                      \
            make_float4(aReg[0], aReg[1], aReg[2], aReg[3]);                   \
        *reinterpret_cast<float4*>(&Bs[(buf)][lk][lw4]) = bReg;                \
    } while (0)

    LOAD_TILE(0);
    STORE_TILE(0);
    __syncthreads();

    const int NSTEP = 9 * 32;  // 288
    for (int kstep = 0; kstep < NSTEP; kstep++) {
        int cur = kstep & 1;
        if (kstep < NSTEP - 1) LOAD_TILE(kstep + 1);

        #pragma unroll
        for (int kk = 0; kk < 8; kk++) {
            float a_frag[8], b_frag[8];
            *reinterpret_cast<float4*>(&a_frag[0]) =
                *reinterpret_cast<const float4*>(&As[cur][kk][ty * 8]);
            *reinterpret_cast<float4*>(&a_frag[4]) =
                *reinterpret_cast<const float4*>(&As[cur][kk][ty * 8 + 4]);
            *reinterpret_cast<float4*>(&b_frag[0]) =
                *reinterpret_cast<const float4*>(&Bs[cur][kk][tx * 8]);
            *reinterpret_cast<float4*>(&b_frag[4]) =
                *reinterpret_cast<const float4*>(&Bs[cur][kk][tx * 8 + 4]);
            #pragma unroll
            for (int i = 0; i < 8; i++)
                #pragma unroll
                for (int j = 0; j < 8; j++)
                    acc[i][j] = fmaf(a_frag[i], b_frag[j], acc[i][j]);
        }

        if (kstep < NSTEP - 1) {
            STORE_TILE(cur ^ 1);
            __syncthreads();
        }
    }

    // ---- epilogue: out[b][oc][h][w] = acc + bias[16*b + oc/16] ----
    // (reference does jnp.repeat(bias,16).reshape(16,256) -> bias_mat[b][oc] =
    //  bias[16*b + oc/16])
    float* ob = out + ((size_t)b * OUT_CH) * (HDIM * WDIM) + (size_t)h * WDIM;
    #pragma unroll
    for (int j = 0; j < 8; j++) {
        int oc   = n0 + tx * 8 + j;
        float bv = bias[(b << 4) + (oc >> 4)];
        float* op = ob + (size_t)oc * (HDIM * WDIM) + ty * 8;
        float4 v0 = make_float4(acc[0][j] + bv, acc[1][j] + bv,
                                acc[2][j] + bv, acc[3][j] + bv);
        float4 v1 = make_float4(acc[4][j] + bv, acc[5][j] + bv,
                                acc[6][j] + bv, acc[7][j] + bv);
        *reinterpret_cast<float4*>(op)     = v0;
        *reinterpret_cast<float4*>(op + 4) = v1;
    }

    #undef LOAD_TILE
    #undef STORE_TILE
}

// ---------------------------------------------------------------------------
// Launch
// Inputs (metadata order): input f32 [16,256,128,128], condition_feature f32
// [16,1,256,1,1], weight f32 [256,256,3,3], bias f32 [256]. Output f32
// [16,256,128,128].
// ---------------------------------------------------------------------------
extern "C" void kernel_launch(void* const* d_in, const int* in_sizes, int n_in,
                              void* d_out, int out_size) {
    const float* x    = (const float*)d_in[0];
    const float* cond = (const float*)d_in[1];
    const float* w    = (const float*)d_in[2];
    const float* bias = (const float*)d_in[3];
    float* out = (float*)d_out;

    const float scale = 1.0f / 48.0f;   // 1/sqrt(256*9), 2304 = 48^2 exactly

    int wt_elems = 9 * IN_CH * OUT_CH;
    weight_transform_kernel<<<(wt_elems + 255) / 256, 256>>>(w, scale);

    dim3 grid(OUT_CH / 128, (BATCH * HDIM * WDIM) / (128 * WDIM) * HDIM);
    // grid = (2, 2048): x = N-tile, y = (b,h) row
    conv_gemm_kernel<<<dim3(2, BATCH * HDIM), 256>>>(x, cond, bias, out);
}

// round 6
// speedup vs baseline: 1.6194x; 1.6194x over previous
#include <cuda_runtime.h>
#include <mma.h>
#include <cstdint>
#include <cstddef>

using namespace nvcuda;

#define IC    256
#define OC    256
#define BATCH 16
#define HDIM  128
#define WDIM  128
#define HP    130
#define WP    130
#define KTOT  2304            // 9 * 256
#define BK    32
#define NPANEL 72             // KTOT / BK
#define NSTAGE 4

#define BM 128
#define BN 128
#define ASTRIDE 36            // 32 + 4 pad (16B multiple)
#define BISTRIDE 136

// smem layout (floats): As[4][128][36] | Bs[4][128][36] | binit[16][136]
#define AS_OFF   0
#define BS_OFF   (NSTAGE * BM * ASTRIDE)            // 18432
#define BI_OFF   (2 * NSTAGE * BM * ASTRIDE)        // 36864
#define SMEM_FLOATS (BI_OFF + 16 * BISTRIDE)        // 39040
#define SMEM_DYN (SMEM_FLOATS * 4)                  // 156160 B

// __device__ scratch (no runtime allocation allowed)
__device__ float g_xmodT[(size_t)BATCH * HP * WP * IC];  // [b][h1][w1][ic], modulated, tf32-rounded, zero halo
__device__ float g_wB[(size_t)OC * KTOT];                // [oc][t*256+ic], scaled 1/48, tf32-rounded

// ---------------------------------------------------------------------------
__device__ __forceinline__ float tf32_rna(float x) {
    uint32_t r;
    asm("cvt.rna.tf32.f32 %0, %1;" : "=r"(r) : "f"(x));
    return __uint_as_float(r);
}
__device__ __forceinline__ uint32_t smem_u32(const void* p) {
    uint32_t a;
    asm("{ .reg .u64 t; cvta.to.shared.u64 t, %1; cvt.u32.u64 %0, t; }" : "=r"(a) : "l"(p));
    return a;
}
#define CP_ASYNC16(dst_u32, src_ptr)                                           \
    asm volatile("cp.async.cg.shared.global [%0], [%1], 16;"                   \
                 :: "r"(dst_u32), "l"(__cvta_generic_to_global(src_ptr)))
#define CP_COMMIT()  asm volatile("cp.async.commit_group;" ::: "memory")
#define CP_WAIT3()   asm volatile("cp.async.wait_group 3;" ::: "memory")

// ---------------------------------------------------------------------------
// Pre-pass 1: zero halo border of g_xmodT
// ---------------------------------------------------------------------------
__global__ void zero_border_kernel() {
    int gid = blockIdx.x * blockDim.x + threadIdx.x;
    const int per_b = 516 * IC;
    if (gid >= BATCH * per_b) return;
    int b   = gid / per_b;
    int rem = gid - b * per_b;
    int p   = rem >> 8;
    int ic  = rem & 255;
    int h1, w1;
    if (p < 260) { h1 = (p < 130) ? 0 : 129; w1 = p % 130; }
    else         { int q = p - 260; h1 = 1 + (q & 127); w1 = (q >> 7) ? 129 : 0; }
    g_xmodT[(((size_t)b * HP + h1) * WP + w1) * IC + ic] = 0.f;
}

// ---------------------------------------------------------------------------
// Pre-pass 2: modulate + transpose + tf32-round
// grid (W/32, IC/64, B*H), block 256
// ---------------------------------------------------------------------------
__global__ __launch_bounds__(256)
void mod_transpose_kernel(const float* __restrict__ x, const float* __restrict__ cond) {
    __shared__ float ts[64][33];
    const int tid = threadIdx.x;
    const int w0  = blockIdx.x << 5;
    const int ic0 = blockIdx.y << 6;
    const int bh  = blockIdx.z;
    const int b   = bh >> 7;
    const int h   = bh & 127;

    #pragma unroll
    for (int i = 0; i < 8; i++) {
        int e = (i << 8) + tid;
        int r = e >> 5, c = e & 31;
        float cv = cond[b * IC + ic0 + r];
        float v  = x[((size_t)(b * IC + ic0 + r) * HDIM + h) * WDIM + w0 + c];
        ts[r][c] = tf32_rna(v * cv);
    }
    __syncthreads();
    #pragma unroll
    for (int i = 0; i < 8; i++) {
        int e  = (i << 8) + tid;
        int wr = e >> 6, cc = e & 63;
        g_xmodT[(((size_t)b * HP + (h + 1)) * WP + (w0 + wr + 1)) * IC + ic0 + cc] = ts[cc][wr];
    }
}

// ---------------------------------------------------------------------------
// Pre-pass 3: weights -> g_wB[oc][t*256+ic], scaled, tf32-rounded
// ---------------------------------------------------------------------------
__global__ void weight_kernel(const float* __restrict__ w) {
    int gid = blockIdx.x * blockDim.x + threadIdx.x;
    if (gid >= OC * KTOT) return;
    int oc = gid / KTOT;
    int k  = gid - oc * KTOT;
    int t  = k >> 8;
    int ic = k & 255;
    g_wB[gid] = tf32_rna(w[(size_t)oc * KTOT + ic * 9 + t] * (1.0f / 48.0f));
}

// ---------------------------------------------------------------------------
// Main kernel: wmma tf32 implicit GEMM, cp.async 4-stage pipeline.
// grid (2, 2048): x = N-tile (128 oc), y = (b,h). 256 threads = 8 warps.
// Warp tile 64x32: warp_m = wid&1 (64 rows), warp_n = wid>>1 (32 cols).
// ---------------------------------------------------------------------------
__global__ __launch_bounds__(256, 1)
void conv_wmma_kernel(const float* __restrict__ bias, float* __restrict__ out) {
    extern __shared__ float sm[];
    float* Asm   = sm + AS_OFF;   // [st][row=m][k]  stride ASTRIDE
    float* Bsm   = sm + BS_OFF;   // [st][row=n][k]  stride ASTRIDE
    float* binit = sm + BI_OFF;   // [16][BISTRIDE], rows identical = bias(n)

    const int tid = threadIdx.x;
    const int wid = tid >> 5;
    const int bh  = blockIdx.y;
    const int b   = bh >> 7;
    const int h   = bh & 127;
    const int n0_blk = blockIdx.x << 7;

    const int warp_m = wid & 1;        // 0..1 -> 64 rows
    const int warp_n = wid >> 1;       // 0..3 -> 32 cols

    const float* xb = g_xmodT + (size_t)b * HP * WP * IC;

    // loader mapping: 1024 16B chunks per tile, 4 per thread
    // task = tid + i*256 ; row = task>>3 (0..127), chunk = task&7
    const uint32_t As_base = smem_u32(Asm);
    const uint32_t Bs_base = smem_u32(Bsm);

    #define ISSUE_PANEL(p, st) do {                                            \
        const int t_   = (p) >> 3;                                             \
        const int ic0_ = ((p) & 7) << 5;                                       \
        const int kh_  = t_ / 3;                                               \
        const int kw_  = t_ - kh_ * 3;                                         \
        const float* asrc = xb + ((size_t)(h + kh_) * WP + kw_) * IC + ic0_;   \
        const float* bsrc = g_wB + (size_t)n0_blk * KTOT + (p) * BK;           \
        const uint32_t ao = As_base + (uint32_t)(st) * (BM * ASTRIDE * 4);     \
        const uint32_t bo = Bs_base + (uint32_t)(st) * (BM * ASTRIDE * 4);     \
        _Pragma("unroll")                                                      \
        for (int i_ = 0; i_ < 4; i_++) {                                       \
            const int task = tid + (i_ << 8);                                  \
            const int row  = task >> 3;                                        \
            const int ch   = task & 7;                                         \
            CP_ASYNC16(ao + (uint32_t)row * (ASTRIDE * 4) + (ch << 4),         \
                       asrc + (size_t)row * IC + (ch << 2));                   \
            CP_ASYNC16(bo + (uint32_t)row * (ASTRIDE * 4) + (ch << 4),         \
                       bsrc + (size_t)row * KTOT + (ch << 2));                 \
        }                                                                      \
    } while (0)

    // binit fill: binit[i][j] = bias[(b<<4) + ((n0_blk+j)>>4)]
    for (int e = tid; e < 16 * 128; e += 256) {
        int i = e >> 7, j = e & 127;
        binit[i * BISTRIDE + j] = bias[(b << 4) + ((n0_blk + j) >> 4)];
    }

    // prologue: panels 0..2
    ISSUE_PANEL(0, 0); CP_COMMIT();
    ISSUE_PANEL(1, 1); CP_COMMIT();
    ISSUE_PANEL(2, 2); CP_COMMIT();
    __syncthreads();   // binit visible

    // accumulators initialized with bias
    wmma::fragment<wmma::accumulator, 16, 16, 8, float> acc[4][2];
    #pragma unroll
    for (int mi = 0; mi < 4; mi++)
        #pragma unroll
        for (int ni = 0; ni < 2; ni++)
            wmma::load_matrix_sync(acc[mi][ni],
                binit + (warp_n * 32 + ni * 16), BISTRIDE, wmma::mem_row_major);

    for (int p = 0; p < NPANEL; p++) {
        if (p + 3 < NPANEL) ISSUE_PANEL(p + 3, (p + 3) & (NSTAGE - 1));
        CP_COMMIT();
        CP_WAIT3();
        __syncthreads();

        const int st = p & (NSTAGE - 1);
        const float* Ab = Asm + st * (BM * ASTRIDE) + (warp_m * 64) * ASTRIDE;
        const float* Bb = Bsm + st * (BM * ASTRIDE) + (warp_n * 32) * ASTRIDE;

        #pragma unroll
        for (int ks = 0; ks < 4; ks++) {
            const int k0 = ks << 3;
            wmma::fragment<wmma::matrix_a, 16, 16, 8, wmma::precision::tf32,
                           wmma::row_major> af[4];
            wmma::fragment<wmma::matrix_b, 16, 16, 8, wmma::precision::tf32,
                           wmma::col_major> bf[2];
            #pragma unroll
            for (int mi = 0; mi < 4; mi++)
                wmma::load_matrix_sync(af[mi], Ab + mi * 16 * ASTRIDE + k0, ASTRIDE);
            #pragma unroll
            for (int ni = 0; ni < 2; ni++)
                wmma::load_matrix_sync(bf[ni], Bb + ni * 16 * ASTRIDE + k0, ASTRIDE);
            #pragma unroll
            for (int mi = 0; mi < 4; mi++)
                #pragma unroll
                for (int ni = 0; ni < 2; ni++)
                    wmma::mma_sync(acc[mi][ni], af[mi], bf[ni], acc[mi][ni]);
        }
        __syncthreads();
    }

    // epilogue: C(m=w, n=oc) at out[b][oc][h][w]; col-major tile store ldm=16384
    #pragma unroll
    for (int ni = 0; ni < 2; ni++) {
        const int ocb = n0_blk + warp_n * 32 + ni * 16;
        #pragma unroll
        for (int mi = 0; mi < 4; mi++) {
            const int wb = warp_m * 64 + mi * 16;
            size_t base = (((size_t)(b * OC + ocb) * HDIM) + h) * WDIM + wb;
            wmma::store_matrix_sync(out + base, acc[mi][ni],
                                    HDIM * WDIM, wmma::mem_col_major);
        }
    }
    #undef ISSUE_PANEL
}

// ---------------------------------------------------------------------------
// Launch. Inputs: input f32 [16,256,128,128], condition f32 [16,1,256,1,1],
// weight f32 [256,256,3,3], bias f32 [256]. Output f32 [16,256,128,128].
// ---------------------------------------------------------------------------
extern "C" void kernel_launch(void* const* d_in, const int* in_sizes, int n_in,
                              void* d_out, int out_size) {
    const float* x    = (const float*)d_in[0];
    const float* cond = (const float*)d_in[1];
    const float* w    = (const float*)d_in[2];
    const float* bias = (const float*)d_in[3];
    float* out = (float*)d_out;

    cudaFuncSetAttribute(conv_wmma_kernel,
                         cudaFuncAttributeMaxDynamicSharedMemorySize, SMEM_DYN);

    {
        int n = BATCH * 516 * IC;
        zero_border_kernel<<<(n + 255) / 256, 256>>>();
    }
    mod_transpose_kernel<<<dim3(WDIM / 32, IC / 64, BATCH * HDIM), 256>>>(x, cond);
    {
        int n = OC * KTOT;
        weight_kernel<<<(n + 255) / 256, 256>>>(w);
    }
    conv_wmma_kernel<<<dim3(2, BATCH * HDIM), 256, SMEM_DYN>>>(bias, out);
}